// round 4
// baseline (speedup 1.0000x reference)
#include <cuda_runtime.h>

#define TM    32      // batch rows per CTA
#define KB    32      // k-chunk staged in smem
#define NTHR  256

// Transposed mid weights: g_Wt[l][k][n] = Ws[l][n][k]  (512x512 each)
__device__ float g_Wt[6][512 * 512];

union f2u { float2 f; unsigned long long u; };

__device__ __forceinline__ void ffma2(f2u& d, const f2u& a, const f2u& b) {
    asm("fma.rn.f32x2 %0, %1, %2, %0;" : "+l"(d.u) : "l"(a.u), "l"(b.u));
}

__device__ __forceinline__ void cp_async16(float* dst_smem, const float* src_gmem) {
    unsigned s = (unsigned)__cvta_generic_to_shared(dst_smem);
    asm volatile("cp.async.cg.shared.global [%0], [%1], 16;" :: "r"(s), "l"(src_gmem));
}
__device__ __forceinline__ void cp_commit() { asm volatile("cp.async.commit_group;"); }
template<int N> __device__ __forceinline__ void cp_wait() {
    asm volatile("cp.async.wait_group %0;" :: "n"(N));
}

// output width of linear layer l (l = 0..6) for factor F
template<int F>
__host__ __device__ constexpr int hdim(int l) {
    return (F == 0) ? 256 : ((F == 2) ? 512 : ((l % 2 == 0) ? 512 : 256));
}

// ---------------- weight transpose prep ----------------
__global__ void prep_transpose(const float* __restrict__ Ws) {
    __shared__ float tile[32][33];
    int l  = blockIdx.z;
    int bk = blockIdx.x * 32;   // k (input dim) tile base
    int bn = blockIdx.y * 32;   // n (output dim) tile base
    int tx = threadIdx.x, ty = threadIdx.y;
    const float* W = Ws + l * 512 * 512;
    #pragma unroll
    for (int i = 0; i < 32; i += 8)
        tile[ty + i][tx] = W[(bn + ty + i) * 512 + bk + tx];   // tile[n_loc][k_loc]
    __syncthreads();
    float* O = g_Wt[l];
    #pragma unroll
    for (int i = 0; i < 32; i += 8)
        O[(bk + ty + i) * 512 + bn + tx] = tile[tx][ty + i];    // O[k][n] = W[n][k]
}

// ---------------- LN + ReLU epilogue: acc regs -> smem act ----------------
template<int HOUT>
__device__ __forceinline__ void ln_relu_store(f2u (&acc)[4][8],
                                              const float* __restrict__ lw,
                                              const float* __restrict__ lb,
                                              float* act, int tx, int ty) {
    constexpr int J2 = HOUT / 64;
    const int n0 = 2 * tx;
    float2 lwv[J2], lbv[J2];
    #pragma unroll
    for (int j = 0; j < J2; ++j) {
        lwv[j] = *reinterpret_cast<const float2*>(lw + n0 + 64 * j);
        lbv[j] = *reinterpret_cast<const float2*>(lb + n0 + 64 * j);
    }
    #pragma unroll
    for (int r = 0; r < 4; ++r) {
        float s = 0.f, q = 0.f;
        #pragma unroll
        for (int j = 0; j < J2; ++j) {
            float2 v = acc[r][j].f;
            s += v.x + v.y;
            q += v.x * v.x + v.y * v.y;
        }
        #pragma unroll
        for (int o = 16; o > 0; o >>= 1) {
            s += __shfl_xor_sync(0xffffffffu, s, o);
            q += __shfl_xor_sync(0xffffffffu, q, o);
        }
        const float mean = s * (1.0f / HOUT);
        const float var  = q * (1.0f / HOUT) - mean * mean;
        const float rstd = rsqrtf(var + 1e-5f);
        float2* arow = reinterpret_cast<float2*>(act + (ty * 4 + r) * 512 + n0);
        #pragma unroll
        for (int j = 0; j < J2; ++j) {
            float2 v = acc[r][j].f;
            float2 o2;
            o2.x = fmaxf((v.x - mean) * rstd * lwv[j].x + lbv[j].x, 0.f);
            o2.y = fmaxf((v.y - mean) * rstd * lwv[j].y + lbv[j].y, 0.f);
            arow[32 * j] = o2;
        }
    }
    __syncthreads();  // act ready for next layer; also protects Bs reuse
}

// ---------------- mid layer: act[TM x HIN] @ Wt -> LN -> ReLU -> act ----------------
template<int HIN, int HOUT>
__device__ __noinline__ void mid_layer(const float* __restrict__ Wt,
                                       const float* __restrict__ bias,
                                       const float* __restrict__ lw,
                                       const float* __restrict__ lb,
                                       int tid, int tx, int ty) {
    extern __shared__ float smem[];
    float* act = smem;                   // [TM][512]
    float* Bs  = smem + TM * 512;        // [2][KB][512]

    constexpr int J2  = HOUT / 64;
    constexpr int NCH = HIN / KB;
    constexpr int NF4 = KB * HOUT / 4 / NTHR;   // float4 copies per thread per chunk

    f2u acc[4][8];
    #pragma unroll
    for (int j = 0; j < J2; ++j) {
        float2 bv = *reinterpret_cast<const float2*>(bias + 2 * tx + 64 * j);
        #pragma unroll
        for (int r = 0; r < 4; ++r) acc[r][j].f = bv;
    }

    // prefetch chunk 0
    #pragma unroll
    for (int t = 0; t < NF4; ++t) {
        int idx = (tid + t * NTHR) * 4;      // float index within chunk (kk major)
        int kk  = idx / HOUT;
        int nf  = idx - kk * HOUT;
        cp_async16(Bs + kk * 512 + nf, Wt + kk * 512 + nf);
    }
    cp_commit();

    for (int c = 0; c < NCH; ++c) {
        if (c + 1 < NCH) {
            const float* src = Wt + (c + 1) * (KB * 512);
            float* dst = Bs + ((c + 1) & 1) * (KB * 512);
            #pragma unroll
            for (int t = 0; t < NF4; ++t) {
                int idx = (tid + t * NTHR) * 4;
                int kk  = idx / HOUT;
                int nf  = idx - kk * HOUT;
                cp_async16(dst + kk * 512 + nf, src + kk * 512 + nf);
            }
            cp_commit();
            cp_wait<1>();
        } else {
            cp_wait<0>();
        }
        __syncthreads();

        const float* B = Bs + (c & 1) * (KB * 512);
        const float* A = act + c * KB;
        #pragma unroll 2
        for (int kk4 = 0; kk4 < KB; kk4 += 4) {
            float4 av[4];
            #pragma unroll
            for (int r = 0; r < 4; ++r)
                av[r] = *reinterpret_cast<const float4*>(A + (ty * 4 + r) * 512 + kk4);
            #pragma unroll
            for (int u = 0; u < 4; ++u) {
                f2u bv[8];
                const float2* Brow = reinterpret_cast<const float2*>(B + (kk4 + u) * 512 + 2 * tx);
                #pragma unroll
                for (int j = 0; j < J2; ++j) bv[j].f = Brow[32 * j];
                #pragma unroll
                for (int r = 0; r < 4; ++r) {
                    float a = (u == 0) ? av[r].x : (u == 1) ? av[r].y : (u == 2) ? av[r].z : av[r].w;
                    f2u a2; a2.f = make_float2(a, a);
                    #pragma unroll
                    for (int j = 0; j < J2; ++j) ffma2(acc[r][j], a2, bv[j]);
                }
            }
        }
        __syncthreads();
    }
    ln_relu_store<HOUT>(acc, lw, lb, act, tx, ty);
}

// ---------------- first layer (K = 6) ----------------
template<int F>
__device__ __forceinline__ void layer0(const float* __restrict__ inputs,
                                       const float* __restrict__ W_in,
                                       const float* __restrict__ b_in,
                                       const float* __restrict__ lw,
                                       const float* __restrict__ lb,
                                       int tid, int tx, int ty, int rowbase) {
    extern __shared__ float smem[];
    float* act = smem;
    float* xin = smem + TM * 512;   // reuse Bs region as input staging
    constexpr int HOUT = hdim<F>(0);
    constexpr int J2 = HOUT / 64;

    if (tid < TM * 6) xin[tid] = inputs[rowbase * 6 + tid];
    __syncthreads();

    f2u acc[4][8];
    #pragma unroll
    for (int j = 0; j < J2; ++j) {
        int n0 = 2 * tx + 64 * j;
        float2 w[6];
        #pragma unroll
        for (int k = 0; k < 6; ++k)
            w[k] = make_float2(W_in[n0 * 6 + k], W_in[(n0 + 1) * 6 + k]);
        float2 bb = make_float2(b_in[n0], b_in[n0 + 1]);
        #pragma unroll
        for (int r = 0; r < 4; ++r) {
            const float* x = xin + (ty * 4 + r) * 6;
            float2 s = bb;
            #pragma unroll
            for (int k = 0; k < 6; ++k) { s.x += x[k] * w[k].x; s.y += x[k] * w[k].y; }
            acc[r][j].f = s;
        }
    }
    __syncthreads();   // xin reads done before Bs is reused by mid layers
    ln_relu_store<HOUT>(acc, lw, lb, act, tx, ty);
}

// ---------------- output layer (3 outputs) ----------------
template<int HIN>
__device__ __forceinline__ void out_layer(const float* __restrict__ W_out,
                                          const float* __restrict__ b_out,
                                          float* __restrict__ out,
                                          int tx, int ty, int rowbase, int fidx) {
    extern __shared__ float smem[];
    const float* act = smem;
    float p[4][3];
    #pragma unroll
    for (int r = 0; r < 4; ++r) p[r][0] = p[r][1] = p[r][2] = 0.f;
    #pragma unroll
    for (int t = 0; t < HIN / 32; ++t) {
        int k = tx + 32 * t;
        float w0 = W_out[k], w1 = W_out[512 + k], w2 = W_out[1024 + k];
        #pragma unroll
        for (int r = 0; r < 4; ++r) {
            float a = act[(ty * 4 + r) * 512 + k];
            p[r][0] += a * w0; p[r][1] += a * w1; p[r][2] += a * w2;
        }
    }
    #pragma unroll
    for (int o = 16; o > 0; o >>= 1) {
        #pragma unroll
        for (int r = 0; r < 4; ++r) {
            p[r][0] += __shfl_xor_sync(0xffffffffu, p[r][0], o);
            p[r][1] += __shfl_xor_sync(0xffffffffu, p[r][1], o);
            p[r][2] += __shfl_xor_sync(0xffffffffu, p[r][2], o);
        }
    }
    if (tx == 0) {
        #pragma unroll
        for (int r = 0; r < 4; ++r) {
            int row = rowbase + ty * 4 + r;
            float* op = out + row * 9 + fidx * 3;
            op[0] = p[r][0] + b_out[0];
            op[1] = p[r][1] + b_out[1];
            op[2] = p[r][2] + b_out[2];
        }
    }
}

// ---------------- main fused kernel per factor ----------------
template<int F>
__global__ void __launch_bounds__(NTHR, 1) mipnet_kernel(
    const float* __restrict__ inputs,
    const float* __restrict__ W_in, const float* __restrict__ b_in,
    const float* __restrict__ bs,
    const float* __restrict__ ln_w, const float* __restrict__ ln_b,
    const float* __restrict__ W_out, const float* __restrict__ b_out,
    float* __restrict__ out)
{
    const int tid = threadIdx.x;
    const int tx = tid & 31;
    const int ty = tid >> 5;
    const int rowbase = blockIdx.x * TM;

    layer0<F>(inputs, W_in, b_in, ln_w, ln_b, tid, tx, ty, rowbase);
    mid_layer<hdim<F>(0), hdim<F>(1)>(g_Wt[0], bs,         ln_w + 512,  ln_b + 512,  tid, tx, ty);
    mid_layer<hdim<F>(1), hdim<F>(2)>(g_Wt[1], bs + 512,   ln_w + 1024, ln_b + 1024, tid, tx, ty);
    mid_layer<hdim<F>(2), hdim<F>(3)>(g_Wt[2], bs + 1024,  ln_w + 1536, ln_b + 1536, tid, tx, ty);
    mid_layer<hdim<F>(3), hdim<F>(4)>(g_Wt[3], bs + 1536,  ln_w + 2048, ln_b + 2048, tid, tx, ty);
    mid_layer<hdim<F>(4), hdim<F>(5)>(g_Wt[4], bs + 2048,  ln_w + 2560, ln_b + 2560, tid, tx, ty);
    mid_layer<hdim<F>(5), hdim<F>(6)>(g_Wt[5], bs + 2560,  ln_w + 3072, ln_b + 3072, tid, tx, ty);
    out_layer<hdim<F>(6)>(W_out, b_out, out, tx, ty, rowbase, F);
}

extern "C" void kernel_launch(void* const* d_in, const int* in_sizes, int n_in,
                              void* d_out, int out_size) {
    const float* inputs = (const float*)d_in[0];
    const float* W_in   = (const float*)d_in[1];
    const float* b_in   = (const float*)d_in[2];
    const float* Ws     = (const float*)d_in[3];
    const float* bs     = (const float*)d_in[4];
    const float* ln_w   = (const float*)d_in[5];
    const float* ln_b   = (const float*)d_in[6];
    const float* W_out  = (const float*)d_in[7];
    const float* b_out  = (const float*)d_in[8];
    float* out = (float*)d_out;

    const int N = in_sizes[0] / 6;
    const int nblk = N / TM;

    {
        dim3 tb(32, 8), tg(16, 16, 6);
        prep_transpose<<<tg, tb>>>(Ws);
    }

    const int smem = (TM * 512 + 2 * KB * 512) * (int)sizeof(float);  // 192 KB
    cudaFuncSetAttribute(mipnet_kernel<0>, cudaFuncAttributeMaxDynamicSharedMemorySize, smem);
    cudaFuncSetAttribute(mipnet_kernel<1>, cudaFuncAttributeMaxDynamicSharedMemorySize, smem);
    cudaFuncSetAttribute(mipnet_kernel<2>, cudaFuncAttributeMaxDynamicSharedMemorySize, smem);

    mipnet_kernel<0><<<nblk, NTHR, smem>>>(inputs, W_in, b_in, bs, ln_w, ln_b, W_out, b_out, out);
    mipnet_kernel<1><<<nblk, NTHR, smem>>>(inputs, W_in, b_in, bs, ln_w, ln_b, W_out, b_out, out);
    mipnet_kernel<2><<<nblk, NTHR, smem>>>(inputs, W_in, b_in, bs, ln_w, ln_b, W_out, b_out, out);
}

// round 5
// speedup vs baseline: 1.1688x; 1.1688x over previous
#include <cuda_runtime.h>

#define TM    32      // batch rows per CTA
#define KB    8       // k-chunk staged in smem (double buffered)
#define NTHR  256

// Transposed mid weights: g_Wt[l][k][n] = Ws[l][n][k]  (512x512 each)
__device__ float g_Wt[6][512 * 512];

union f2u { float2 f; unsigned long long u; };

__device__ __forceinline__ void ffma2(f2u& d, const f2u& a, const f2u& b) {
    asm("fma.rn.f32x2 %0, %1, %2, %0;" : "+l"(d.u) : "l"(a.u), "l"(b.u));
}

__device__ __forceinline__ void cp_async16(float* dst_smem, const float* src_gmem) {
    unsigned s = (unsigned)__cvta_generic_to_shared(dst_smem);
    asm volatile("cp.async.cg.shared.global [%0], [%1], 16;" :: "r"(s), "l"(src_gmem));
}
__device__ __forceinline__ void cp_commit() { asm volatile("cp.async.commit_group;"); }
template<int N> __device__ __forceinline__ void cp_wait() {
    asm volatile("cp.async.wait_group %0;" :: "n"(N));
}

// output width of linear layer l (l = 0..6) for factor F
template<int F>
__host__ __device__ constexpr int hdim(int l) {
    return (F == 0) ? 256 : ((F == 2) ? 512 : ((l % 2 == 0) ? 512 : 256));
}

// smem layout (floats): act[TM*512] | Bs[2*KB*512] | red[2*32*2]
#define ACT_F   (TM * 512)
#define BS_F    (2 * KB * 512)
#define RED_F   (2 * 32 * 2)
#define SMEM_F  (ACT_F + BS_F + RED_F)

// ---------------- weight transpose prep ----------------
__global__ void prep_transpose(const float* __restrict__ Ws) {
    __shared__ float tile[32][33];
    int l  = blockIdx.z;
    int bk = blockIdx.x * 32;
    int bn = blockIdx.y * 32;
    int tx = threadIdx.x, ty = threadIdx.y;
    const float* W = Ws + l * 512 * 512;
    #pragma unroll
    for (int i = 0; i < 32; i += 8)
        tile[ty + i][tx] = W[(bn + ty + i) * 512 + bk + tx];
    __syncthreads();
    float* O = g_Wt[l];
    #pragma unroll
    for (int i = 0; i < 32; i += 8)
        O[(bk + ty + i) * 512 + bn + tx] = tile[tx][ty + i];
}

// ---------------- LN + ReLU epilogue (cross-half reduction) ----------------
// warp (cy, ry) owns rows [ry*8, ry*8+8) and cols [cy*HOUT/2, (cy+1)*HOUT/2)
template<int HOUT>
__device__ __forceinline__ void ln_relu_store(f2u (&acc)[8][HOUT / 128],
                                              const float* __restrict__ lw,
                                              const float* __restrict__ lb,
                                              float* act, float* red,
                                              int tx, int cy, int ry) {
    constexpr int J2 = HOUT / 128;
    const int n0 = cy * (HOUT / 2) + 2 * tx;

    float sr[8], qr[8];
    #pragma unroll
    for (int r = 0; r < 8; ++r) {
        float s = 0.f, q = 0.f;
        #pragma unroll
        for (int j = 0; j < J2; ++j) {
            float2 v = acc[r][j].f;
            s += v.x + v.y;
            q += v.x * v.x + v.y * v.y;
        }
        #pragma unroll
        for (int o = 16; o > 0; o >>= 1) {
            s += __shfl_xor_sync(0xffffffffu, s, o);
            q += __shfl_xor_sync(0xffffffffu, q, o);
        }
        sr[r] = s; qr[r] = q;
        if (tx == 0) {
            red[(cy * 32 + ry * 8 + r) * 2 + 0] = s;
            red[(cy * 32 + ry * 8 + r) * 2 + 1] = q;
        }
    }
    __syncthreads();

    float2 lwv[J2], lbv[J2];
    #pragma unroll
    for (int j = 0; j < J2; ++j) {
        lwv[j] = *reinterpret_cast<const float2*>(lw + n0 + 64 * j);
        lbv[j] = *reinterpret_cast<const float2*>(lb + n0 + 64 * j);
    }
    #pragma unroll
    for (int r = 0; r < 8; ++r) {
        const int rowg = ry * 8 + r;
        const float s = sr[r] + red[((cy ^ 1) * 32 + rowg) * 2 + 0];
        const float q = qr[r] + red[((cy ^ 1) * 32 + rowg) * 2 + 1];
        const float mean = s * (1.0f / HOUT);
        const float var  = q * (1.0f / HOUT) - mean * mean;
        const float rstd = rsqrtf(var + 1e-5f);
        float2* arow = reinterpret_cast<float2*>(act + rowg * 512 + n0);
        #pragma unroll
        for (int j = 0; j < J2; ++j) {
            float2 v = acc[r][j].f;
            float2 o2;
            o2.x = fmaxf((v.x - mean) * rstd * lwv[j].x + lbv[j].x, 0.f);
            o2.y = fmaxf((v.y - mean) * rstd * lwv[j].y + lbv[j].y, 0.f);
            arow[32 * j] = o2;
        }
    }
    __syncthreads();   // act ready; Bs/red safe for reuse
}

// ---------------- mid layer: act[TM x HIN] @ Wt -> LN -> ReLU -> act ----------------
template<int HIN, int HOUT>
__device__ __noinline__ void mid_layer(const float* __restrict__ Wt,
                                       const float* __restrict__ bias,
                                       const float* __restrict__ lw,
                                       const float* __restrict__ lb,
                                       int tid, int tx, int cy, int ry) {
    extern __shared__ float smem[];
    float* act = smem;
    float* Bs  = smem + ACT_F;
    float* red = smem + ACT_F + BS_F;

    constexpr int J2  = HOUT / 128;
    constexpr int NCH = HIN / KB;
    constexpr int NF4 = KB * HOUT / 4 / NTHR;

    const int n0 = cy * (HOUT / 2) + 2 * tx;

    f2u acc[8][J2];
    #pragma unroll
    for (int j = 0; j < J2; ++j) {
        float2 bv = *reinterpret_cast<const float2*>(bias + n0 + 64 * j);
        #pragma unroll
        for (int r = 0; r < 8; ++r) acc[r][j].f = bv;
    }

    // prefetch chunk 0
    #pragma unroll
    for (int t = 0; t < NF4; ++t) {
        int idx = (tid + t * NTHR) * 4;
        int kk  = idx / HOUT;
        int nf  = idx - kk * HOUT;
        cp_async16(Bs + kk * 512 + nf, Wt + kk * 512 + nf);
    }
    cp_commit();

    for (int c = 0; c < NCH; ++c) {
        cp_wait<0>();
        __syncthreads();      // chunk c visible; all warps done with buffer (c+1)&1
        if (c + 1 < NCH) {    // safe to overwrite (c+1)&1 now
            const float* src = Wt + (c + 1) * (KB * 512);
            float* dst = Bs + ((c + 1) & 1) * (KB * 512);
            #pragma unroll
            for (int t = 0; t < NF4; ++t) {
                int idx = (tid + t * NTHR) * 4;
                int kk  = idx / HOUT;
                int nf  = idx - kk * HOUT;
                cp_async16(dst + kk * 512 + nf, src + kk * 512 + nf);
            }
            cp_commit();
        }

        const float* B = Bs + (c & 1) * (KB * 512);
        const float* A = act + c * KB + (ry * 8) * 512;
        #pragma unroll
        for (int kp = 0; kp < KB / 2; ++kp) {
            float2 av[8];
            #pragma unroll
            for (int r = 0; r < 8; ++r)
                av[r] = *reinterpret_cast<const float2*>(A + r * 512 + 2 * kp);
            #pragma unroll
            for (int u = 0; u < 2; ++u) {
                f2u bv[J2];
                const float2* Brow = reinterpret_cast<const float2*>(B + (2 * kp + u) * 512 + n0);
                #pragma unroll
                for (int j = 0; j < J2; ++j) bv[j].f = Brow[32 * j];
                #pragma unroll
                for (int r = 0; r < 8; ++r) {
                    float a = u ? av[r].y : av[r].x;
                    f2u a2; a2.f = make_float2(a, a);
                    #pragma unroll
                    for (int j = 0; j < J2; ++j) ffma2(acc[r][j], a2, bv[j]);
                }
            }
        }
    }
    ln_relu_store<HOUT>(acc, lw, lb, act, red, tx, cy, ry);
}

// ---------------- first layer (K = 6) ----------------
template<int F>
__device__ __forceinline__ void layer0(const float* __restrict__ inputs,
                                       const float* __restrict__ W_in,
                                       const float* __restrict__ b_in,
                                       const float* __restrict__ lw,
                                       const float* __restrict__ lb,
                                       int tid, int tx, int cy, int ry, int rowbase) {
    extern __shared__ float smem[];
    float* act = smem;
    float* xin = smem + ACT_F;            // reuse Bs region
    float* red = smem + ACT_F + BS_F;
    constexpr int HOUT = hdim<F>(0);
    constexpr int J2 = HOUT / 128;
    const int n0 = cy * (HOUT / 2) + 2 * tx;

    if (tid < TM * 6) xin[tid] = inputs[rowbase * 6 + tid];
    __syncthreads();

    f2u acc[8][J2];
    #pragma unroll
    for (int j = 0; j < J2; ++j) {
        const int n = n0 + 64 * j;
        float2 w[6];
        #pragma unroll
        for (int k = 0; k < 6; ++k)
            w[k] = make_float2(W_in[n * 6 + k], W_in[(n + 1) * 6 + k]);
        float2 bb = make_float2(b_in[n], b_in[n + 1]);
        #pragma unroll
        for (int r = 0; r < 8; ++r) {
            const float* x = xin + (ry * 8 + r) * 6;
            float2 s = bb;
            #pragma unroll
            for (int k = 0; k < 6; ++k) { s.x += x[k] * w[k].x; s.y += x[k] * w[k].y; }
            acc[r][j].f = s;
        }
    }
    // xin reads complete before ln's first barrier; Bs reuse happens after ln's final barrier
    ln_relu_store<HOUT>(acc, lw, lb, act, red, tx, cy, ry);
}

// ---------------- output layer (3 outputs) ----------------
template<int HIN>
__device__ __forceinline__ void out_layer(const float* __restrict__ W_out,
                                          const float* __restrict__ b_out,
                                          float* __restrict__ out,
                                          int tx, int ty, int rowbase, int fidx) {
    extern __shared__ float smem[];
    const float* act = smem;
    float p[4][3];
    #pragma unroll
    for (int r = 0; r < 4; ++r) p[r][0] = p[r][1] = p[r][2] = 0.f;
    #pragma unroll
    for (int t = 0; t < HIN / 32; ++t) {
        int k = tx + 32 * t;
        float w0 = W_out[k], w1 = W_out[512 + k], w2 = W_out[1024 + k];
        #pragma unroll
        for (int r = 0; r < 4; ++r) {
            float a = act[(ty * 4 + r) * 512 + k];
            p[r][0] += a * w0; p[r][1] += a * w1; p[r][2] += a * w2;
        }
    }
    #pragma unroll
    for (int o = 16; o > 0; o >>= 1) {
        #pragma unroll
        for (int r = 0; r < 4; ++r) {
            p[r][0] += __shfl_xor_sync(0xffffffffu, p[r][0], o);
            p[r][1] += __shfl_xor_sync(0xffffffffu, p[r][1], o);
            p[r][2] += __shfl_xor_sync(0xffffffffu, p[r][2], o);
        }
    }
    if (tx == 0) {
        #pragma unroll
        for (int r = 0; r < 4; ++r) {
            int row = rowbase + ty * 4 + r;
            float* op = out + row * 9 + fidx * 3;
            op[0] = p[r][0] + b_out[0];
            op[1] = p[r][1] + b_out[1];
            op[2] = p[r][2] + b_out[2];
        }
    }
}

// ---------------- main fused kernel per factor ----------------
template<int F>
__global__ void __launch_bounds__(NTHR, 2) mipnet_kernel(
    const float* __restrict__ inputs,
    const float* __restrict__ W_in, const float* __restrict__ b_in,
    const float* __restrict__ bs,
    const float* __restrict__ ln_w, const float* __restrict__ ln_b,
    const float* __restrict__ W_out, const float* __restrict__ b_out,
    float* __restrict__ out)
{
    const int tid = threadIdx.x;
    const int tx  = tid & 31;
    const int wid = tid >> 5;
    const int cy  = wid & 1;     // column half
    const int ry  = wid >> 1;    // row group (8 rows)
    const int rowbase = blockIdx.x * TM;

    layer0<F>(inputs, W_in, b_in, ln_w, ln_b, tid, tx, cy, ry, rowbase);
    mid_layer<hdim<F>(0), hdim<F>(1)>(g_Wt[0], bs,        ln_w + 512,  ln_b + 512,  tid, tx, cy, ry);
    mid_layer<hdim<F>(1), hdim<F>(2)>(g_Wt[1], bs + 512,  ln_w + 1024, ln_b + 1024, tid, tx, cy, ry);
    mid_layer<hdim<F>(2), hdim<F>(3)>(g_Wt[2], bs + 1024, ln_w + 1536, ln_b + 1536, tid, tx, cy, ry);
    mid_layer<hdim<F>(3), hdim<F>(4)>(g_Wt[3], bs + 1536, ln_w + 2048, ln_b + 2048, tid, tx, cy, ry);
    mid_layer<hdim<F>(4), hdim<F>(5)>(g_Wt[4], bs + 2048, ln_w + 2560, ln_b + 2560, tid, tx, cy, ry);
    mid_layer<hdim<F>(5), hdim<F>(6)>(g_Wt[5], bs + 2560, ln_w + 3072, ln_b + 3072, tid, tx, cy, ry);
    out_layer<hdim<F>(6)>(W_out, b_out, out, tx, wid, rowbase, F);
}

extern "C" void kernel_launch(void* const* d_in, const int* in_sizes, int n_in,
                              void* d_out, int out_size) {
    const float* inputs = (const float*)d_in[0];
    const float* W_in   = (const float*)d_in[1];
    const float* b_in   = (const float*)d_in[2];
    const float* Ws     = (const float*)d_in[3];
    const float* bs     = (const float*)d_in[4];
    const float* ln_w   = (const float*)d_in[5];
    const float* ln_b   = (const float*)d_in[6];
    const float* W_out  = (const float*)d_in[7];
    const float* b_out  = (const float*)d_in[8];
    float* out = (float*)d_out;

    const int N = in_sizes[0] / 6;
    const int nblk = N / TM;

    {
        dim3 tb(32, 8), tg(16, 16, 6);
        prep_transpose<<<tg, tb>>>(Ws);
    }

    const int smem = SMEM_F * (int)sizeof(float);   // 98,816 B
    cudaFuncSetAttribute(mipnet_kernel<0>, cudaFuncAttributeMaxDynamicSharedMemorySize, smem);
    cudaFuncSetAttribute(mipnet_kernel<1>, cudaFuncAttributeMaxDynamicSharedMemorySize, smem);
    cudaFuncSetAttribute(mipnet_kernel<2>, cudaFuncAttributeMaxDynamicSharedMemorySize, smem);

    mipnet_kernel<0><<<nblk, NTHR, smem>>>(inputs, W_in, b_in, bs, ln_w, ln_b, W_out, b_out, out);
    mipnet_kernel<1><<<nblk, NTHR, smem>>>(inputs, W_in, b_in, bs, ln_w, ln_b, W_out, b_out, out);
    mipnet_kernel<2><<<nblk, NTHR, smem>>>(inputs, W_in, b_in, bs, ln_w, ln_b, W_out, b_out, out);
}

// round 6
// speedup vs baseline: 1.1701x; 1.0011x over previous
#include <cuda_runtime.h>

#define TM    32      // batch rows per CTA
#define KB    8       // k-chunk staged in smem (double buffered)
#define NTHR  256

// Transposed mid weights: g_Wt[l][k][n] = Ws[l][n][k]  (512x512 each)
__device__ float g_Wt[6][512 * 512];

union f2u { float2 f; unsigned long long u; };

__device__ __forceinline__ void ffma2(f2u& d, const f2u& a, const f2u& b) {
    asm("fma.rn.f32x2 %0, %1, %2, %0;" : "+l"(d.u) : "l"(a.u), "l"(b.u));
}

__device__ __forceinline__ void cp_async16(float* dst_smem, const float* src_gmem) {
    unsigned s = (unsigned)__cvta_generic_to_shared(dst_smem);
    asm volatile("cp.async.cg.shared.global [%0], [%1], 16;" :: "r"(s), "l"(src_gmem));
}
__device__ __forceinline__ void cp_commit() { asm volatile("cp.async.commit_group;"); }
template<int N> __device__ __forceinline__ void cp_wait() {
    asm volatile("cp.async.wait_group %0;" :: "n"(N));
}

// output width of linear layer l (l = 0..6) for factor F
template<int F>
__host__ __device__ constexpr int hdim(int l) {
    return (F == 0) ? 256 : ((F == 2) ? 512 : ((l % 2 == 0) ? 512 : 256));
}

// smem layout (floats): act[TM*512] | Bs[2*KB*512] | red[2*32*2]
#define ACT_F   (TM * 512)
#define BS_F    (2 * KB * 512)
#define RED_F   (2 * 32 * 2)
#define SMEM_F  (ACT_F + BS_F + RED_F)

// ---------------- weight transpose prep ----------------
__global__ void prep_transpose(const float* __restrict__ Ws) {
    __shared__ float tile[32][33];
    int l  = blockIdx.z;
    int bk = blockIdx.x * 32;
    int bn = blockIdx.y * 32;
    int tx = threadIdx.x, ty = threadIdx.y;
    const float* W = Ws + l * 512 * 512;
    #pragma unroll
    for (int i = 0; i < 32; i += 8)
        tile[ty + i][tx] = W[(bn + ty + i) * 512 + bk + tx];
    __syncthreads();
    float* O = g_Wt[l];
    #pragma unroll
    for (int i = 0; i < 32; i += 8)
        O[(bk + ty + i) * 512 + bn + tx] = tile[tx][ty + i];
}

// ---------------- LN + ReLU epilogue (cross-half reduction) ----------------
// warp (cy, ry) owns rows [ry*8, ry*8+8) and cols [cy*HOUT/2, (cy+1)*HOUT/2)
template<int HOUT>
__device__ __forceinline__ void ln_relu_store(f2u (&acc)[8][HOUT / 128],
                                              const float* __restrict__ lw,
                                              const float* __restrict__ lb,
                                              float* act, float* red,
                                              int tx, int cy, int ry) {
    constexpr int J2 = HOUT / 128;
    const int n0 = cy * (HOUT / 2) + 2 * tx;

    float sr[8], qr[8];
    #pragma unroll
    for (int r = 0; r < 8; ++r) {
        float s = 0.f, q = 0.f;
        #pragma unroll
        for (int j = 0; j < J2; ++j) {
            float2 v = acc[r][j].f;
            s += v.x + v.y;
            q += v.x * v.x + v.y * v.y;
        }
        #pragma unroll
        for (int o = 16; o > 0; o >>= 1) {
            s += __shfl_xor_sync(0xffffffffu, s, o);
            q += __shfl_xor_sync(0xffffffffu, q, o);
        }
        sr[r] = s; qr[r] = q;
        if (tx == 0) {
            red[(cy * 32 + ry * 8 + r) * 2 + 0] = s;
            red[(cy * 32 + ry * 8 + r) * 2 + 1] = q;
        }
    }
    __syncthreads();

    float2 lwv[J2], lbv[J2];
    #pragma unroll
    for (int j = 0; j < J2; ++j) {
        lwv[j] = *reinterpret_cast<const float2*>(lw + n0 + 64 * j);
        lbv[j] = *reinterpret_cast<const float2*>(lb + n0 + 64 * j);
    }
    #pragma unroll
    for (int r = 0; r < 8; ++r) {
        const int rowg = ry * 8 + r;
        const float s = sr[r] + red[((cy ^ 1) * 32 + rowg) * 2 + 0];
        const float q = qr[r] + red[((cy ^ 1) * 32 + rowg) * 2 + 1];
        const float mean = s * (1.0f / HOUT);
        const float var  = q * (1.0f / HOUT) - mean * mean;
        const float rstd = rsqrtf(var + 1e-5f);
        float2* arow = reinterpret_cast<float2*>(act + rowg * 512 + n0);
        #pragma unroll
        for (int j = 0; j < J2; ++j) {
            float2 v = acc[r][j].f;
            float2 o2;
            o2.x = fmaxf((v.x - mean) * rstd * lwv[j].x + lbv[j].x, 0.f);
            o2.y = fmaxf((v.y - mean) * rstd * lwv[j].y + lbv[j].y, 0.f);
            arow[32 * j] = o2;
        }
    }
    __syncthreads();   // act ready; Bs/red safe for reuse
}

// ---------------- mid layer: act[TM x HIN] @ Wt -> LN -> ReLU -> act ----------------
template<int HIN, int HOUT>
__device__ __noinline__ void mid_layer(const float* __restrict__ Wt,
                                       const float* __restrict__ bias,
                                       const float* __restrict__ lw,
                                       const float* __restrict__ lb,
                                       int tid, int tx, int cy, int ry) {
    extern __shared__ float smem[];
    float* act = smem;
    float* Bs  = smem + ACT_F;
    float* red = smem + ACT_F + BS_F;

    constexpr int J2  = HOUT / 128;
    constexpr int NCH = HIN / KB;
    constexpr int NF4 = KB * HOUT / 4 / NTHR;

    const int n0 = cy * (HOUT / 2) + 2 * tx;

    f2u acc[8][J2];
    #pragma unroll
    for (int j = 0; j < J2; ++j) {
        float2 bv = *reinterpret_cast<const float2*>(bias + n0 + 64 * j);
        #pragma unroll
        for (int r = 0; r < 8; ++r) acc[r][j].f = bv;
    }

    // prefetch chunk 0
    #pragma unroll
    for (int t = 0; t < NF4; ++t) {
        int idx = (tid + t * NTHR) * 4;
        int kk  = idx / HOUT;
        int nf  = idx - kk * HOUT;
        cp_async16(Bs + kk * 512 + nf, Wt + kk * 512 + nf);
    }
    cp_commit();

    for (int c = 0; c < NCH; ++c) {
        cp_wait<0>();
        __syncthreads();      // chunk c visible; all warps done with buffer (c+1)&1
        if (c + 1 < NCH) {    // safe to overwrite (c+1)&1 now
            const float* src = Wt + (c + 1) * (KB * 512);
            float* dst = Bs + ((c + 1) & 1) * (KB * 512);
            #pragma unroll
            for (int t = 0; t < NF4; ++t) {
                int idx = (tid + t * NTHR) * 4;
                int kk  = idx / HOUT;
                int nf  = idx - kk * HOUT;
                cp_async16(dst + kk * 512 + nf, src + kk * 512 + nf);
            }
            cp_commit();
        }

        const float* B = Bs + (c & 1) * (KB * 512);
        const float* A = act + c * KB + (ry * 8) * 512;
        #pragma unroll
        for (int kp = 0; kp < KB / 2; ++kp) {
            float2 av[8];
            #pragma unroll
            for (int r = 0; r < 8; ++r)
                av[r] = *reinterpret_cast<const float2*>(A + r * 512 + 2 * kp);
            #pragma unroll
            for (int u = 0; u < 2; ++u) {
                f2u bv[J2];
                const float2* Brow = reinterpret_cast<const float2*>(B + (2 * kp + u) * 512 + n0);
                #pragma unroll
                for (int j = 0; j < J2; ++j) bv[j].f = Brow[32 * j];
                #pragma unroll
                for (int r = 0; r < 8; ++r) {
                    float a = u ? av[r].y : av[r].x;
                    f2u a2; a2.f = make_float2(a, a);
                    #pragma unroll
                    for (int j = 0; j < J2; ++j) ffma2(acc[r][j], a2, bv[j]);
                }
            }
        }
    }
    ln_relu_store<HOUT>(acc, lw, lb, act, red, tx, cy, ry);
}

// ---------------- first layer (K = 6) ----------------
template<int F>
__device__ __forceinline__ void layer0(const float* __restrict__ inputs,
                                       const float* __restrict__ W_in,
                                       const float* __restrict__ b_in,
                                       const float* __restrict__ lw,
                                       const float* __restrict__ lb,
                                       int tid, int tx, int cy, int ry, int rowbase) {
    extern __shared__ float smem[];
    float* act = smem;
    float* xin = smem + ACT_F;            // reuse Bs region
    float* red = smem + ACT_F + BS_F;
    constexpr int HOUT = hdim<F>(0);
    constexpr int J2 = HOUT / 128;
    const int n0 = cy * (HOUT / 2) + 2 * tx;

    if (tid < TM * 6) xin[tid] = inputs[rowbase * 6 + tid];
    __syncthreads();

    f2u acc[8][J2];
    #pragma unroll
    for (int j = 0; j < J2; ++j) {
        const int n = n0 + 64 * j;
        float2 w[6];
        #pragma unroll
        for (int k = 0; k < 6; ++k)
            w[k] = make_float2(W_in[n * 6 + k], W_in[(n + 1) * 6 + k]);
        float2 bb = make_float2(b_in[n], b_in[n + 1]);
        #pragma unroll
        for (int r = 0; r < 8; ++r) {
            const float* x = xin + (ry * 8 + r) * 6;
            float2 s = bb;
            #pragma unroll
            for (int k = 0; k < 6; ++k) { s.x += x[k] * w[k].x; s.y += x[k] * w[k].y; }
            acc[r][j].f = s;
        }
    }
    // xin reads complete before ln's first barrier; Bs reuse happens after ln's final barrier
    ln_relu_store<HOUT>(acc, lw, lb, act, red, tx, cy, ry);
}

// ---------------- output layer (3 outputs) ----------------
template<int HIN>
__device__ __forceinline__ void out_layer(const float* __restrict__ W_out,
                                          const float* __restrict__ b_out,
                                          float* __restrict__ out,
                                          int tx, int ty, int rowbase, int fidx) {
    extern __shared__ float smem[];
    const float* act = smem;
    float p[4][3];
    #pragma unroll
    for (int r = 0; r < 4; ++r) p[r][0] = p[r][1] = p[r][2] = 0.f;
    #pragma unroll
    for (int t = 0; t < HIN / 32; ++t) {
        int k = tx + 32 * t;
        float w0 = W_out[k], w1 = W_out[512 + k], w2 = W_out[1024 + k];
        #pragma unroll
        for (int r = 0; r < 4; ++r) {
            float a = act[(ty * 4 + r) * 512 + k];
            p[r][0] += a * w0; p[r][1] += a * w1; p[r][2] += a * w2;
        }
    }
    #pragma unroll
    for (int o = 16; o > 0; o >>= 1) {
        #pragma unroll
        for (int r = 0; r < 4; ++r) {
            p[r][0] += __shfl_xor_sync(0xffffffffu, p[r][0], o);
            p[r][1] += __shfl_xor_sync(0xffffffffu, p[r][1], o);
            p[r][2] += __shfl_xor_sync(0xffffffffu, p[r][2], o);
        }
    }
    if (tx == 0) {
        #pragma unroll
        for (int r = 0; r < 4; ++r) {
            int row = rowbase + ty * 4 + r;
            float* op = out + row * 9 + fidx * 3;
            op[0] = p[r][0] + b_out[0];
            op[1] = p[r][1] + b_out[1];
            op[2] = p[r][2] + b_out[2];
        }
    }
}

// ---------------- main fused kernel per factor ----------------
template<int F>
__global__ void __launch_bounds__(NTHR, 2) mipnet_kernel(
    const float* __restrict__ inputs,
    const float* __restrict__ W_in, const float* __restrict__ b_in,
    const float* __restrict__ bs,
    const float* __restrict__ ln_w, const float* __restrict__ ln_b,
    const float* __restrict__ W_out, const float* __restrict__ b_out,
    float* __restrict__ out)
{
    const int tid = threadIdx.x;
    const int tx  = tid & 31;
    const int wid = tid >> 5;
    const int cy  = wid & 1;     // column half
    const int ry  = wid >> 1;    // row group (8 rows)
    const int rowbase = blockIdx.x * TM;

    layer0<F>(inputs, W_in, b_in, ln_w, ln_b, tid, tx, cy, ry, rowbase);
    mid_layer<hdim<F>(0), hdim<F>(1)>(g_Wt[0], bs,        ln_w + 512,  ln_b + 512,  tid, tx, cy, ry);
    mid_layer<hdim<F>(1), hdim<F>(2)>(g_Wt[1], bs + 512,  ln_w + 1024, ln_b + 1024, tid, tx, cy, ry);
    mid_layer<hdim<F>(2), hdim<F>(3)>(g_Wt[2], bs + 1024, ln_w + 1536, ln_b + 1536, tid, tx, cy, ry);
    mid_layer<hdim<F>(3), hdim<F>(4)>(g_Wt[3], bs + 1536, ln_w + 2048, ln_b + 2048, tid, tx, cy, ry);
    mid_layer<hdim<F>(4), hdim<F>(5)>(g_Wt[4], bs + 2048, ln_w + 2560, ln_b + 2560, tid, tx, cy, ry);
    mid_layer<hdim<F>(5), hdim<F>(6)>(g_Wt[5], bs + 2560, ln_w + 3072, ln_b + 3072, tid, tx, cy, ry);
    out_layer<hdim<F>(6)>(W_out, b_out, out, tx, wid, rowbase, F);
}

extern "C" void kernel_launch(void* const* d_in, const int* in_sizes, int n_in,
                              void* d_out, int out_size) {
    const float* inputs = (const float*)d_in[0];
    const float* W_in   = (const float*)d_in[1];
    const float* b_in   = (const float*)d_in[2];
    const float* Ws     = (const float*)d_in[3];
    const float* bs     = (const float*)d_in[4];
    const float* ln_w   = (const float*)d_in[5];
    const float* ln_b   = (const float*)d_in[6];
    const float* W_out  = (const float*)d_in[7];
    const float* b_out  = (const float*)d_in[8];
    float* out = (float*)d_out;

    const int N = in_sizes[0] / 6;
    const int nblk = N / TM;

    {
        dim3 tb(32, 8), tg(16, 16, 6);
        prep_transpose<<<tg, tb>>>(Ws);
    }

    const int smem = SMEM_F * (int)sizeof(float);   // 98,816 B
    cudaFuncSetAttribute(mipnet_kernel<0>, cudaFuncAttributeMaxDynamicSharedMemorySize, smem);
    cudaFuncSetAttribute(mipnet_kernel<1>, cudaFuncAttributeMaxDynamicSharedMemorySize, smem);
    cudaFuncSetAttribute(mipnet_kernel<2>, cudaFuncAttributeMaxDynamicSharedMemorySize, smem);

    mipnet_kernel<0><<<nblk, NTHR, smem>>>(inputs, W_in, b_in, bs, ln_w, ln_b, W_out, b_out, out);
    mipnet_kernel<1><<<nblk, NTHR, smem>>>(inputs, W_in, b_in, bs, ln_w, ln_b, W_out, b_out, out);
    mipnet_kernel<2><<<nblk, NTHR, smem>>>(inputs, W_in, b_in, bs, ln_w, ln_b, W_out, b_out, out);
}

// round 7
// speedup vs baseline: 1.1706x; 1.0004x over previous
#include <cuda_runtime.h>

#define TM    32      // batch rows per CTA
#define KB    8       // k-chunk staged in smem (double buffered)
#define NTHR  256

// Transposed mid weights: g_Wt[l][k][n] = Ws[l][n][k]  (512x512 each)
__device__ float g_Wt[6][512 * 512];

union f2u { float2 f; unsigned long long u; };

__device__ __forceinline__ void ffma2(f2u& d, const f2u& a, const f2u& b) {
    asm("fma.rn.f32x2 %0, %1, %2, %0;" : "+l"(d.u) : "l"(a.u), "l"(b.u));
}

__device__ __forceinline__ void cp_async16(float* dst_smem, const float* src_gmem) {
    unsigned s = (unsigned)__cvta_generic_to_shared(dst_smem);
    asm volatile("cp.async.cg.shared.global [%0], [%1], 16;" :: "r"(s), "l"(src_gmem));
}
__device__ __forceinline__ void cp_commit() { asm volatile("cp.async.commit_group;"); }
template<int N> __device__ __forceinline__ void cp_wait() {
    asm volatile("cp.async.wait_group %0;" :: "n"(N));
}

// output width of linear layer l (l = 0..6) for factor F
template<int F>
__host__ __device__ constexpr int hdim(int l) {
    return (F == 0) ? 256 : ((F == 2) ? 512 : ((l % 2 == 0) ? 512 : 256));
}

// smem layout (floats): act[TM*512] | Bs[2*KB*512] | red[2*32*2]
#define ACT_F   (TM * 512)
#define BS_F    (2 * KB * 512)
#define RED_F   (2 * 32 * 2)
#define SMEM_F  (ACT_F + BS_F + RED_F)

// ---------------- weight transpose prep ----------------
__global__ void prep_transpose(const float* __restrict__ Ws) {
    __shared__ float tile[32][33];
    int l  = blockIdx.z;
    int bk = blockIdx.x * 32;
    int bn = blockIdx.y * 32;
    int tx = threadIdx.x, ty = threadIdx.y;
    const float* W = Ws + l * 512 * 512;
    #pragma unroll
    for (int i = 0; i < 32; i += 8)
        tile[ty + i][tx] = W[(bn + ty + i) * 512 + bk + tx];
    __syncthreads();
    float* O = g_Wt[l];
    #pragma unroll
    for (int i = 0; i < 32; i += 8)
        O[(bk + ty + i) * 512 + bn + tx] = tile[tx][ty + i];
}

// ---------------- LN + ReLU epilogue (cross-half reduction) ----------------
// warp (cy, ry) owns rows [ry*8, ry*8+8) and cols [cy*HOUT/2, (cy+1)*HOUT/2)
template<int HOUT>
__device__ __forceinline__ void ln_relu_store(f2u (&acc)[8][HOUT / 128],
                                              const float* __restrict__ lw,
                                              const float* __restrict__ lb,
                                              float* act, float* red,
                                              int tx, int cy, int ry) {
    constexpr int J2 = HOUT / 128;
    const int n0 = cy * (HOUT / 2) + 2 * tx;

    float sr[8], qr[8];
    #pragma unroll
    for (int r = 0; r < 8; ++r) {
        float s = 0.f, q = 0.f;
        #pragma unroll
        for (int j = 0; j < J2; ++j) {
            float2 v = acc[r][j].f;
            s += v.x + v.y;
            q += v.x * v.x + v.y * v.y;
        }
        #pragma unroll
        for (int o = 16; o > 0; o >>= 1) {
            s += __shfl_xor_sync(0xffffffffu, s, o);
            q += __shfl_xor_sync(0xffffffffu, q, o);
        }
        sr[r] = s; qr[r] = q;
        if (tx == 0) {
            red[(cy * 32 + ry * 8 + r) * 2 + 0] = s;
            red[(cy * 32 + ry * 8 + r) * 2 + 1] = q;
        }
    }
    __syncthreads();

    float2 lwv[J2], lbv[J2];
    #pragma unroll
    for (int j = 0; j < J2; ++j) {
        lwv[j] = *reinterpret_cast<const float2*>(lw + n0 + 64 * j);
        lbv[j] = *reinterpret_cast<const float2*>(lb + n0 + 64 * j);
    }
    #pragma unroll
    for (int r = 0; r < 8; ++r) {
        const int rowg = ry * 8 + r;
        const float s = sr[r] + red[((cy ^ 1) * 32 + rowg) * 2 + 0];
        const float q = qr[r] + red[((cy ^ 1) * 32 + rowg) * 2 + 1];
        const float mean = s * (1.0f / HOUT);
        const float var  = q * (1.0f / HOUT) - mean * mean;
        const float rstd = rsqrtf(var + 1e-5f);
        float2* arow = reinterpret_cast<float2*>(act + rowg * 512 + n0);
        #pragma unroll
        for (int j = 0; j < J2; ++j) {
            float2 v = acc[r][j].f;
            float2 o2;
            o2.x = fmaxf((v.x - mean) * rstd * lwv[j].x + lbv[j].x, 0.f);
            o2.y = fmaxf((v.y - mean) * rstd * lwv[j].y + lbv[j].y, 0.f);
            arow[32 * j] = o2;
        }
    }
    __syncthreads();   // act ready; Bs/red safe for reuse
}

// ---------------- mid layer: act[TM x HIN] @ Wt -> LN -> ReLU -> act ----------------
template<int HIN, int HOUT>
__device__ __noinline__ void mid_layer(const float* __restrict__ Wt,
                                       const float* __restrict__ bias,
                                       const float* __restrict__ lw,
                                       const float* __restrict__ lb,
                                       int tid, int tx, int cy, int ry) {
    extern __shared__ float smem[];
    float* act = smem;
    float* Bs  = smem + ACT_F;
    float* red = smem + ACT_F + BS_F;

    constexpr int J2  = HOUT / 128;
    constexpr int NCH = HIN / KB;
    constexpr int NF4 = KB * HOUT / 4 / NTHR;

    const int n0 = cy * (HOUT / 2) + 2 * tx;

    f2u acc[8][J2];
    #pragma unroll
    for (int j = 0; j < J2; ++j) {
        float2 bv = *reinterpret_cast<const float2*>(bias + n0 + 64 * j);
        #pragma unroll
        for (int r = 0; r < 8; ++r) acc[r][j].f = bv;
    }

    // prefetch chunk 0
    #pragma unroll
    for (int t = 0; t < NF4; ++t) {
        int idx = (tid + t * NTHR) * 4;
        int kk  = idx / HOUT;
        int nf  = idx - kk * HOUT;
        cp_async16(Bs + kk * 512 + nf, Wt + kk * 512 + nf);
    }
    cp_commit();

    for (int c = 0; c < NCH; ++c) {
        cp_wait<0>();
        __syncthreads();      // chunk c visible; all warps done with buffer (c+1)&1
        if (c + 1 < NCH) {    // safe to overwrite (c+1)&1 now
            const float* src = Wt + (c + 1) * (KB * 512);
            float* dst = Bs + ((c + 1) & 1) * (KB * 512);
            #pragma unroll
            for (int t = 0; t < NF4; ++t) {
                int idx = (tid + t * NTHR) * 4;
                int kk  = idx / HOUT;
                int nf  = idx - kk * HOUT;
                cp_async16(dst + kk * 512 + nf, src + kk * 512 + nf);
            }
            cp_commit();
        }

        const float* B = Bs + (c & 1) * (KB * 512);
        const float* A = act + c * KB + (ry * 8) * 512;
        #pragma unroll
        for (int kp = 0; kp < KB / 2; ++kp) {
            float2 av[8];
            #pragma unroll
            for (int r = 0; r < 8; ++r)
                av[r] = *reinterpret_cast<const float2*>(A + r * 512 + 2 * kp);
            #pragma unroll
            for (int u = 0; u < 2; ++u) {
                f2u bv[J2];
                const float2* Brow = reinterpret_cast<const float2*>(B + (2 * kp + u) * 512 + n0);
                #pragma unroll
                for (int j = 0; j < J2; ++j) bv[j].f = Brow[32 * j];
                #pragma unroll
                for (int r = 0; r < 8; ++r) {
                    float a = u ? av[r].y : av[r].x;
                    f2u a2; a2.f = make_float2(a, a);
                    #pragma unroll
                    for (int j = 0; j < J2; ++j) ffma2(acc[r][j], a2, bv[j]);
                }
            }
        }
    }
    ln_relu_store<HOUT>(acc, lw, lb, act, red, tx, cy, ry);
}

// ---------------- first layer (K = 6) ----------------
template<int F>
__device__ __forceinline__ void layer0(const float* __restrict__ inputs,
                                       const float* __restrict__ W_in,
                                       const float* __restrict__ b_in,
                                       const float* __restrict__ lw,
                                       const float* __restrict__ lb,
                                       int tid, int tx, int cy, int ry, int rowbase) {
    extern __shared__ float smem[];
    float* act = smem;
    float* xin = smem + ACT_F;            // reuse Bs region
    float* red = smem + ACT_F + BS_F;
    constexpr int HOUT = hdim<F>(0);
    constexpr int J2 = HOUT / 128;
    const int n0 = cy * (HOUT / 2) + 2 * tx;

    if (tid < TM * 6) xin[tid] = inputs[rowbase * 6 + tid];
    __syncthreads();

    f2u acc[8][J2];
    #pragma unroll
    for (int j = 0; j < J2; ++j) {
        const int n = n0 + 64 * j;
        float2 w[6];
        #pragma unroll
        for (int k = 0; k < 6; ++k)
            w[k] = make_float2(W_in[n * 6 + k], W_in[(n + 1) * 6 + k]);
        float2 bb = make_float2(b_in[n], b_in[n + 1]);
        #pragma unroll
        for (int r = 0; r < 8; ++r) {
            const float* x = xin + (ry * 8 + r) * 6;
            float2 s = bb;
            #pragma unroll
            for (int k = 0; k < 6; ++k) { s.x += x[k] * w[k].x; s.y += x[k] * w[k].y; }
            acc[r][j].f = s;
        }
    }
    // xin reads complete before ln's first barrier; Bs reuse happens after ln's final barrier
    ln_relu_store<HOUT>(acc, lw, lb, act, red, tx, cy, ry);
}

// ---------------- output layer (3 outputs) ----------------
template<int HIN>
__device__ __forceinline__ void out_layer(const float* __restrict__ W_out,
                                          const float* __restrict__ b_out,
                                          float* __restrict__ out,
                                          int tx, int ty, int rowbase, int fidx) {
    extern __shared__ float smem[];
    const float* act = smem;
    float p[4][3];
    #pragma unroll
    for (int r = 0; r < 4; ++r) p[r][0] = p[r][1] = p[r][2] = 0.f;
    #pragma unroll
    for (int t = 0; t < HIN / 32; ++t) {
        int k = tx + 32 * t;
        float w0 = W_out[k], w1 = W_out[512 + k], w2 = W_out[1024 + k];
        #pragma unroll
        for (int r = 0; r < 4; ++r) {
            float a = act[(ty * 4 + r) * 512 + k];
            p[r][0] += a * w0; p[r][1] += a * w1; p[r][2] += a * w2;
        }
    }
    #pragma unroll
    for (int o = 16; o > 0; o >>= 1) {
        #pragma unroll
        for (int r = 0; r < 4; ++r) {
            p[r][0] += __shfl_xor_sync(0xffffffffu, p[r][0], o);
            p[r][1] += __shfl_xor_sync(0xffffffffu, p[r][1], o);
            p[r][2] += __shfl_xor_sync(0xffffffffu, p[r][2], o);
        }
    }
    if (tx == 0) {
        #pragma unroll
        for (int r = 0; r < 4; ++r) {
            int row = rowbase + ty * 4 + r;
            float* op = out + row * 9 + fidx * 3;
            op[0] = p[r][0] + b_out[0];
            op[1] = p[r][1] + b_out[1];
            op[2] = p[r][2] + b_out[2];
        }
    }
}

// ---------------- main fused kernel per factor ----------------
template<int F>
__global__ void __launch_bounds__(NTHR, 2) mipnet_kernel(
    const float* __restrict__ inputs,
    const float* __restrict__ W_in, const float* __restrict__ b_in,
    const float* __restrict__ bs,
    const float* __restrict__ ln_w, const float* __restrict__ ln_b,
    const float* __restrict__ W_out, const float* __restrict__ b_out,
    float* __restrict__ out)
{
    const int tid = threadIdx.x;
    const int tx  = tid & 31;
    const int wid = tid >> 5;
    const int cy  = wid & 1;     // column half
    const int ry  = wid >> 1;    // row group (8 rows)
    const int rowbase = blockIdx.x * TM;

    layer0<F>(inputs, W_in, b_in, ln_w, ln_b, tid, tx, cy, ry, rowbase);
    mid_layer<hdim<F>(0), hdim<F>(1)>(g_Wt[0], bs,        ln_w + 512,  ln_b + 512,  tid, tx, cy, ry);
    mid_layer<hdim<F>(1), hdim<F>(2)>(g_Wt[1], bs + 512,  ln_w + 1024, ln_b + 1024, tid, tx, cy, ry);
    mid_layer<hdim<F>(2), hdim<F>(3)>(g_Wt[2], bs + 1024, ln_w + 1536, ln_b + 1536, tid, tx, cy, ry);
    mid_layer<hdim<F>(3), hdim<F>(4)>(g_Wt[3], bs + 1536, ln_w + 2048, ln_b + 2048, tid, tx, cy, ry);
    mid_layer<hdim<F>(4), hdim<F>(5)>(g_Wt[4], bs + 2048, ln_w + 2560, ln_b + 2560, tid, tx, cy, ry);
    mid_layer<hdim<F>(5), hdim<F>(6)>(g_Wt[5], bs + 2560, ln_w + 3072, ln_b + 3072, tid, tx, cy, ry);
    out_layer<hdim<F>(6)>(W_out, b_out, out, tx, wid, rowbase, F);
}

extern "C" void kernel_launch(void* const* d_in, const int* in_sizes, int n_in,
                              void* d_out, int out_size) {
    const float* inputs = (const float*)d_in[0];
    const float* W_in   = (const float*)d_in[1];
    const float* b_in   = (const float*)d_in[2];
    const float* Ws     = (const float*)d_in[3];
    const float* bs     = (const float*)d_in[4];
    const float* ln_w   = (const float*)d_in[5];
    const float* ln_b   = (const float*)d_in[6];
    const float* W_out  = (const float*)d_in[7];
    const float* b_out  = (const float*)d_in[8];
    float* out = (float*)d_out;

    const int N = in_sizes[0] / 6;
    const int nblk = N / TM;

    {
        dim3 tb(32, 8), tg(16, 16, 6);
        prep_transpose<<<tg, tb>>>(Ws);
    }

    const int smem = SMEM_F * (int)sizeof(float);   // 98,816 B
    cudaFuncSetAttribute(mipnet_kernel<0>, cudaFuncAttributeMaxDynamicSharedMemorySize, smem);
    cudaFuncSetAttribute(mipnet_kernel<1>, cudaFuncAttributeMaxDynamicSharedMemorySize, smem);
    cudaFuncSetAttribute(mipnet_kernel<2>, cudaFuncAttributeMaxDynamicSharedMemorySize, smem);

    mipnet_kernel<0><<<nblk, NTHR, smem>>>(inputs, W_in, b_in, bs, ln_w, ln_b, W_out, b_out, out);
    mipnet_kernel<1><<<nblk, NTHR, smem>>>(inputs, W_in, b_in, bs, ln_w, ln_b, W_out, b_out, out);
    mipnet_kernel<2><<<nblk, NTHR, smem>>>(inputs, W_in, b_in, bs, ln_w, ln_b, W_out, b_out, out);
}